// round 2
// baseline (speedup 1.0000x reference)
#include <cuda_runtime.h>
#include <cuda_bf16.h>
#include <cstdint>

#define BATCH 8
#define CDIM  512
#define NDIM  4096
#define MDIM  1024

// Scratch in __device__ globals (no allocations allowed).
__device__ float g_q[(size_t)BATCH * CDIM * NDIM];   // 64 MB
__device__ float g_k[(size_t)BATCH * CDIM * MDIM];   // 16 MB
__device__ float g_v[(size_t)BATCH * CDIM * MDIM];   // 16 MB
__device__ float g_e[(size_t)BATCH * NDIM * MDIM];   // 128 MB

// ---------------------------------------------------------------------------
// PTX helpers
// ---------------------------------------------------------------------------
__device__ __forceinline__ uint32_t sptr(const void* p) {
    return (uint32_t)__cvta_generic_to_shared(p);
}

__device__ __forceinline__ void ldm_x4(uint32_t& r0, uint32_t& r1,
                                       uint32_t& r2, uint32_t& r3, uint32_t a) {
    asm volatile("ldmatrix.sync.aligned.m8n8.x4.shared.b16 {%0,%1,%2,%3}, [%4];\n"
                 : "=r"(r0), "=r"(r1), "=r"(r2), "=r"(r3) : "r"(a));
}

__device__ __forceinline__ void mma_bf16(float& c0, float& c1, float& c2, float& c3,
                                         uint32_t a0, uint32_t a1, uint32_t a2, uint32_t a3,
                                         uint32_t b0, uint32_t b1) {
    asm volatile("mma.sync.aligned.m16n8k16.row.col.f32.bf16.bf16.f32 "
                 "{%0,%1,%2,%3}, {%4,%5,%6,%7}, {%8,%9}, {%0,%1,%2,%3};\n"
                 : "+f"(c0), "+f"(c1), "+f"(c2), "+f"(c3)
                 : "r"(a0), "r"(a1), "r"(a2), "r"(a3), "r"(b0), "r"(b1));
}

__device__ __forceinline__ void split1(float x, __nv_bfloat16& h, __nv_bfloat16& l) {
    h = __float2bfloat16(x);
    l = __float2bfloat16(x - __bfloat162float(h));
}

// ---------------------------------------------------------------------------
// Split-bf16 tensor-core GEMM: C[i,j] (+)= alpha * sum_k opA(i,k)*opB(k,j)
//   TA=false: A[i*lda+k] ; TA=true: A[k*lda+i]
//   TB=false: B[k*ldb+j] ; TB=true: B[j*ldb+k]
// Block 128x128, BK=32, 256 threads (8 warps, each 32x64).
// fp32 ~= 3x bf16 MMA: Ahi*Bhi + Ahi*Blo + Alo*Bhi.
// All dims are multiples of 128/32 in this problem.
// ---------------------------------------------------------------------------
template<bool TA, bool TB, bool ACC>
__global__ __launch_bounds__(256)
void bgemm(const float* __restrict__ Ag, const float* __restrict__ Bg,
           float* __restrict__ Cg, int Kdim, int lda, int ldb, int ldc,
           size_t sA, size_t sB, size_t sC, float alpha)
{
    constexpr int LDK = 40;   // padded k-stride in halves (80B rows: ldmatrix conflict-free)
    __shared__ __nv_bfloat16 sAhi[128 * LDK];
    __shared__ __nv_bfloat16 sAlo[128 * LDK];
    __shared__ __nv_bfloat16 sBhi[128 * LDK];
    __shared__ __nv_bfloat16 sBlo[128 * LDK];

    const float* A = Ag + blockIdx.z * sA;
    const float* B = Bg + blockIdx.z * sB;
    float*       C = Cg + blockIdx.z * sC;

    const int bx = blockIdx.x, by = blockIdx.y;
    const int tid = threadIdx.x;
    const int lane = tid & 31, wid = tid >> 5;
    const int m_off = (wid & 3) * 32;     // warp M offset within block tile
    const int n_off = (wid >> 2) * 64;    // warp N offset

    float acc[2][8][4];
#pragma unroll
    for (int t = 0; t < 2; t++)
#pragma unroll
        for (int n = 0; n < 8; n++)
#pragma unroll
            for (int r = 0; r < 4; r++) acc[t][n][r] = 0.f;

    // ldmatrix base offsets for this lane (row group + k group)
    const int lrow = lane & 15;
    const int lkof = (lane >> 4) * 8;

    for (int k0 = 0; k0 < Kdim; k0 += 32) {
        // ---------------- stage A tile [128 rows][32 k] as hi/lo ----------------
        if (!TA) {
            // A[i*lda + k]: k-contiguous, direct
#pragma unroll
            for (int p = 0; p < 4; p++) {
                int r = p * 32 + (tid >> 3);
                int c = (tid & 7) * 4;
                float4 v = *(const float4*)&A[(size_t)(by * 128 + r) * lda + k0 + c];
                __nv_bfloat16 h0, l0, h1, l1, h2, l2, h3, l3;
                split1(v.x, h0, l0); split1(v.y, h1, l1);
                split1(v.z, h2, l2); split1(v.w, h3, l3);
                __nv_bfloat162* ph = (__nv_bfloat162*)&sAhi[r * LDK + c];
                __nv_bfloat162* pl = (__nv_bfloat162*)&sAlo[r * LDK + c];
                ph[0] = __nv_bfloat162(h0, h1); ph[1] = __nv_bfloat162(h2, h3);
                pl[0] = __nv_bfloat162(l0, l1); pl[1] = __nv_bfloat162(l2, l3);
            }
        } else {
            // A[k*lda + i]: i-contiguous, transpose into smem [i][k]
#pragma unroll
            for (int p = 0; p < 4; p++) {
                int kk = p * 8 + (tid >> 5);
                int i = (tid & 31) * 4;
                float4 v = *(const float4*)&A[(size_t)(k0 + kk) * lda + by * 128 + i];
                __nv_bfloat16 h, l;
                split1(v.x, h, l); sAhi[(i + 0) * LDK + kk] = h; sAlo[(i + 0) * LDK + kk] = l;
                split1(v.y, h, l); sAhi[(i + 1) * LDK + kk] = h; sAlo[(i + 1) * LDK + kk] = l;
                split1(v.z, h, l); sAhi[(i + 2) * LDK + kk] = h; sAlo[(i + 2) * LDK + kk] = l;
                split1(v.w, h, l); sAhi[(i + 3) * LDK + kk] = h; sAlo[(i + 3) * LDK + kk] = l;
            }
        }
        // ---------------- stage B tile [128 j][32 k] as hi/lo ----------------
        if (TB) {
            // B[j*ldb + k]: k-contiguous, direct
#pragma unroll
            for (int p = 0; p < 4; p++) {
                int r = p * 32 + (tid >> 3);
                int c = (tid & 7) * 4;
                float4 v = *(const float4*)&B[(size_t)(bx * 128 + r) * ldb + k0 + c];
                __nv_bfloat16 h0, l0, h1, l1, h2, l2, h3, l3;
                split1(v.x, h0, l0); split1(v.y, h1, l1);
                split1(v.z, h2, l2); split1(v.w, h3, l3);
                __nv_bfloat162* ph = (__nv_bfloat162*)&sBhi[r * LDK + c];
                __nv_bfloat162* pl = (__nv_bfloat162*)&sBlo[r * LDK + c];
                ph[0] = __nv_bfloat162(h0, h1); ph[1] = __nv_bfloat162(h2, h3);
                pl[0] = __nv_bfloat162(l0, l1); pl[1] = __nv_bfloat162(l2, l3);
            }
        } else {
            // B[k*ldb + j]: j-contiguous, transpose into smem [j][k]
#pragma unroll
            for (int p = 0; p < 4; p++) {
                int kk = p * 8 + (tid >> 5);
                int j = (tid & 31) * 4;
                float4 v = *(const float4*)&B[(size_t)(k0 + kk) * ldb + bx * 128 + j];
                __nv_bfloat16 h, l;
                split1(v.x, h, l); sBhi[(j + 0) * LDK + kk] = h; sBlo[(j + 0) * LDK + kk] = l;
                split1(v.y, h, l); sBhi[(j + 1) * LDK + kk] = h; sBlo[(j + 1) * LDK + kk] = l;
                split1(v.z, h, l); sBhi[(j + 2) * LDK + kk] = h; sBlo[(j + 2) * LDK + kk] = l;
                split1(v.w, h, l); sBhi[(j + 3) * LDK + kk] = h; sBlo[(j + 3) * LDK + kk] = l;
            }
        }
        __syncthreads();

        // ---------------- compute: 2 k16 sub-steps ----------------
#pragma unroll
        for (int ks = 0; ks < 32; ks += 16) {
            uint32_t ahi[2][4], alo[2][4];
#pragma unroll
            for (int t = 0; t < 2; t++) {
                uint32_t ah = sptr(&sAhi[(m_off + t * 16 + lrow) * LDK + ks + lkof]);
                ldm_x4(ahi[t][0], ahi[t][1], ahi[t][2], ahi[t][3], ah);
                uint32_t al = sptr(&sAlo[(m_off + t * 16 + lrow) * LDK + ks + lkof]);
                ldm_x4(alo[t][0], alo[t][1], alo[t][2], alo[t][3], al);
            }
            uint32_t bhi[8][2], blo[8][2];
#pragma unroll
            for (int p = 0; p < 4; p++) {
                uint32_t r0, r1, r2, r3;
                uint32_t bh = sptr(&sBhi[(n_off + p * 16 + lrow) * LDK + ks + lkof]);
                ldm_x4(r0, r1, r2, r3, bh);
                bhi[2 * p][0] = r0; bhi[2 * p][1] = r2;
                bhi[2 * p + 1][0] = r1; bhi[2 * p + 1][1] = r3;
                uint32_t bl = sptr(&sBlo[(n_off + p * 16 + lrow) * LDK + ks + lkof]);
                ldm_x4(r0, r1, r2, r3, bl);
                blo[2 * p][0] = r0; blo[2 * p][1] = r2;
                blo[2 * p + 1][0] = r1; blo[2 * p + 1][1] = r3;
            }
#pragma unroll
            for (int t = 0; t < 2; t++) {
#pragma unroll
                for (int n = 0; n < 8; n++) {
                    float* c = acc[t][n];
                    mma_bf16(c[0], c[1], c[2], c[3],
                             ahi[t][0], ahi[t][1], ahi[t][2], ahi[t][3],
                             bhi[n][0], bhi[n][1]);
                    mma_bf16(c[0], c[1], c[2], c[3],
                             ahi[t][0], ahi[t][1], ahi[t][2], ahi[t][3],
                             blo[n][0], blo[n][1]);
                    mma_bf16(c[0], c[1], c[2], c[3],
                             alo[t][0], alo[t][1], alo[t][2], alo[t][3],
                             bhi[n][0], bhi[n][1]);
                }
            }
        }
        __syncthreads();
    }

    // ---------------- epilogue ----------------
#pragma unroll
    for (int t = 0; t < 2; t++) {
#pragma unroll
        for (int n = 0; n < 8; n++) {
            int mg = by * 128 + m_off + t * 16 + (lane >> 2);
            int ng = bx * 128 + n_off + n * 8 + (lane & 3) * 2;
            float* p0 = &C[(size_t)mg * ldc + ng];
            float* p1 = &C[(size_t)(mg + 8) * ldc + ng];
            float2 o0 = make_float2(acc[t][n][0] * alpha, acc[t][n][1] * alpha);
            float2 o1 = make_float2(acc[t][n][2] * alpha, acc[t][n][3] * alpha);
            if (ACC) {
                float2 q0 = *(const float2*)p0;
                float2 q1 = *(const float2*)p1;
                o0.x += q0.x; o0.y += q0.y;
                o1.x += q1.x; o1.y += q1.y;
            }
            *(float2*)p0 = o0;
            *(float2*)p1 = o1;
        }
    }
}

// ---------------------------------------------------------------------------
// Row softmax over MDIM=1024 columns. One block (256 threads) per row.
// ---------------------------------------------------------------------------
__global__ __launch_bounds__(256)
void softmax_rows(float* __restrict__ e)
{
    __shared__ float red[8];
    const size_t row = blockIdx.x;
    float* p = e + row * (size_t)MDIM;
    const int tid = threadIdx.x;

    float4 v4 = ((const float4*)p)[tid];

    float m = fmaxf(fmaxf(v4.x, v4.y), fmaxf(v4.z, v4.w));
#pragma unroll
    for (int o = 16; o > 0; o >>= 1)
        m = fmaxf(m, __shfl_xor_sync(0xffffffffu, m, o));
    if ((tid & 31) == 0) red[tid >> 5] = m;
    __syncthreads();
    if (tid < 32) {
        float t = (tid < 8) ? red[tid] : -3.4e38f;
#pragma unroll
        for (int o = 4; o > 0; o >>= 1)
            t = fmaxf(t, __shfl_xor_sync(0xffffffffu, t, o));
        if (tid == 0) red[0] = t;
    }
    __syncthreads();
    m = red[0];
    __syncthreads();

    v4.x = __expf(v4.x - m);
    v4.y = __expf(v4.y - m);
    v4.z = __expf(v4.z - m);
    v4.w = __expf(v4.w - m);
    float s = v4.x + v4.y + v4.z + v4.w;
#pragma unroll
    for (int o = 16; o > 0; o >>= 1)
        s += __shfl_xor_sync(0xffffffffu, s, o);
    if ((tid & 31) == 0) red[tid >> 5] = s;
    __syncthreads();
    if (tid < 32) {
        float t = (tid < 8) ? red[tid] : 0.f;
#pragma unroll
        for (int o = 4; o > 0; o >>= 1)
            t += __shfl_xor_sync(0xffffffffu, t, o);
        if (tid == 0) red[0] = t;
    }
    __syncthreads();
    float inv = 1.0f / red[0];

    v4.x *= inv; v4.y *= inv; v4.z *= inv; v4.w *= inv;
    ((float4*)p)[tid] = v4;
}

// ---------------------------------------------------------------------------
extern "C" void kernel_launch(void* const* d_in, const int* in_sizes, int n_in,
                              void* d_out, int out_size)
{
    const float* pcd_up   = (const float*)d_in[0]; // [B, C, N]
    const float* pcd_down = (const float*)d_in[1]; // [B, C, M]
    const float* Wq    = (const float*)d_in[2];    // [C, C]
    const float* Wk    = (const float*)d_in[3];
    const float* Wv    = (const float*)d_in[4];
    const float* Wskip = (const float*)d_in[5];
    float* out = (float*)d_out;                    // [B, C, N]

    float* q;  cudaGetSymbolAddress((void**)&q, g_q);
    float* k;  cudaGetSymbolAddress((void**)&k, g_k);
    float* v;  cudaGetSymbolAddress((void**)&v, g_v);
    float* e;  cudaGetSymbolAddress((void**)&e, g_e);

    const size_t sUp = (size_t)CDIM * NDIM;
    const size_t sDn = (size_t)CDIM * MDIM;
    const size_t sE  = (size_t)NDIM * MDIM;

    dim3 thr(256);
    const float invSqrtC = 0.044194173824159216f; // 1/sqrt(512)

    // q = Wq @ pcd_up ; skip = Wskip @ pcd_up -> out
    {
        dim3 grid(NDIM / 128, CDIM / 128, BATCH);
        bgemm<false, false, false><<<grid, thr>>>(Wq, pcd_up, q,
            CDIM, CDIM, NDIM, NDIM, 0, sUp, sUp, 1.0f);
        bgemm<false, false, false><<<grid, thr>>>(Wskip, pcd_up, out,
            CDIM, CDIM, NDIM, NDIM, 0, sUp, sUp, 1.0f);
    }
    // k = Wk @ pcd_down ; v = Wv @ pcd_down
    {
        dim3 grid(MDIM / 128, CDIM / 128, BATCH);
        bgemm<false, false, false><<<grid, thr>>>(Wk, pcd_down, k,
            CDIM, CDIM, MDIM, MDIM, 0, sDn, sDn, 1.0f);
        bgemm<false, false, false><<<grid, thr>>>(Wv, pcd_down, v,
            CDIM, CDIM, MDIM, MDIM, 0, sDn, sDn, 1.0f);
    }
    // energy[n,m] = (1/sqrt(C)) * sum_c q[c,n] k[c,m]
    {
        dim3 grid(MDIM / 128, NDIM / 128, BATCH);
        bgemm<true, false, false><<<grid, thr>>>(q, k, e,
            CDIM, NDIM, MDIM, MDIM, sUp, sDn, sE, invSqrtC);
    }
    // softmax over m, in place
    softmax_rows<<<BATCH * NDIM, 256>>>(e);

    // out[c,n] += sum_m v[c,m] * attn[n,m]
    {
        dim3 grid(NDIM / 128, CDIM / 128, BATCH);
        bgemm<false, true, true><<<grid, thr>>>(v, e, out,
            MDIM, MDIM, MDIM, NDIM, sDn, sE, sUp, 1.0f);
    }
}

// round 3
// speedup vs baseline: 2.1644x; 2.1644x over previous
#include <cuda_runtime.h>
#include <cuda_bf16.h>
#include <cstdint>

#define BATCH 8
#define CDIM  512
#define NDIM  4096
#define MDIM  1024

typedef __nv_bfloat16  bf16;
typedef __nv_bfloat162 bf162;

// ---------------- scratch (__device__ globals; no allocation allowed) ------
__device__ bf16 g_wh[4 * CDIM * CDIM];                  // Wq,Wk,Wv,Wskip hi
__device__ bf16 g_wl[4 * CDIM * CDIM];                  // lo
__device__ bf16 g_xuh[(size_t)BATCH * CDIM * NDIM];     // pcd_up hi
__device__ bf16 g_xul[(size_t)BATCH * CDIM * NDIM];
__device__ bf16 g_xdh[(size_t)BATCH * CDIM * MDIM];     // pcd_down hi
__device__ bf16 g_xdl[(size_t)BATCH * CDIM * MDIM];
__device__ bf16 g_qh[(size_t)BATCH * CDIM * NDIM];
__device__ bf16 g_ql[(size_t)BATCH * CDIM * NDIM];
__device__ bf16 g_kh[(size_t)BATCH * CDIM * MDIM];
__device__ bf16 g_kl[(size_t)BATCH * CDIM * MDIM];
__device__ bf16 g_vh[(size_t)BATCH * CDIM * MDIM];
__device__ bf16 g_vl[(size_t)BATCH * CDIM * MDIM];
__device__ float g_e[(size_t)BATCH * NDIM * MDIM];      // energy fp32
__device__ bf16 g_ah[(size_t)BATCH * NDIM * MDIM];      // attention hi
__device__ bf16 g_al[(size_t)BATCH * NDIM * MDIM];      // attention lo

// ---------------- PTX helpers ---------------------------------------------
__device__ __forceinline__ uint32_t sptr(const void* p) {
    return (uint32_t)__cvta_generic_to_shared(p);
}
__device__ __forceinline__ void cpa16(void* dst, const void* src) {
    asm volatile("cp.async.cg.shared.global [%0], [%1], 16;\n"
                 :: "r"(sptr(dst)), "l"(src));
}
__device__ __forceinline__ void cpcommit() {
    asm volatile("cp.async.commit_group;\n");
}
template<int N> __device__ __forceinline__ void cpwait() {
    asm volatile("cp.async.wait_group %0;\n" :: "n"(N));
}
__device__ __forceinline__ void ldm_x4(uint32_t& r0, uint32_t& r1,
                                       uint32_t& r2, uint32_t& r3, uint32_t a) {
    asm volatile("ldmatrix.sync.aligned.m8n8.x4.shared.b16 {%0,%1,%2,%3}, [%4];\n"
                 : "=r"(r0), "=r"(r1), "=r"(r2), "=r"(r3) : "r"(a));
}
__device__ __forceinline__ void ldm_x4_t(uint32_t& r0, uint32_t& r1,
                                         uint32_t& r2, uint32_t& r3, uint32_t a) {
    asm volatile("ldmatrix.sync.aligned.m8n8.x4.trans.shared.b16 {%0,%1,%2,%3}, [%4];\n"
                 : "=r"(r0), "=r"(r1), "=r"(r2), "=r"(r3) : "r"(a));
}
__device__ __forceinline__ void mma_bf16(float& c0, float& c1, float& c2, float& c3,
                                         uint32_t a0, uint32_t a1, uint32_t a2, uint32_t a3,
                                         uint32_t b0, uint32_t b1) {
    asm volatile("mma.sync.aligned.m16n8k16.row.col.f32.bf16.bf16.f32 "
                 "{%0,%1,%2,%3}, {%4,%5,%6,%7}, {%8,%9}, {%0,%1,%2,%3};\n"
                 : "+f"(c0), "+f"(c1), "+f"(c2), "+f"(c3)
                 : "r"(a0), "r"(a1), "r"(a2), "r"(a3), "r"(b0), "r"(b1));
}

// ---------------- elementwise split: fp32 -> (hi, lo) bf16 -----------------
__global__ __launch_bounds__(256)
void splitf(const float* __restrict__ x, bf16* __restrict__ hi,
            bf16* __restrict__ lo, size_t n4)
{
    size_t i = (size_t)blockIdx.x * blockDim.x + threadIdx.x;
    if (i >= n4) return;
    float4 v = ((const float4*)x)[i];
    bf16 h0 = __float2bfloat16(v.x), h1 = __float2bfloat16(v.y);
    bf16 h2 = __float2bfloat16(v.z), h3 = __float2bfloat16(v.w);
    bf16 l0 = __float2bfloat16(v.x - __bfloat162float(h0));
    bf16 l1 = __float2bfloat16(v.y - __bfloat162float(h1));
    bf16 l2 = __float2bfloat16(v.z - __bfloat162float(h2));
    bf16 l3 = __float2bfloat16(v.w - __bfloat162float(h3));
    ((bf162*)hi)[2 * i]     = bf162(h0, h1);
    ((bf162*)hi)[2 * i + 1] = bf162(h2, h3);
    ((bf162*)lo)[2 * i]     = bf162(l0, l1);
    ((bf162*)lo)[2 * i + 1] = bf162(l2, l3);
}

// ---------------------------------------------------------------------------
// Split-bf16 tensor-core GEMM with cp.async double buffering.
//   C[i,j] (+)= alpha * sum_k A(i,k)*B(k,j), computed as Ah*Bh + Ah*Bl + Al*Bh.
// AM=0: A stored [i][k] (k contig, lda) -> smem [i][k] LDK=40, normal ldmatrix
// AM=1: A stored [k][i] (i contig)      -> smem [k][i] LDI=136, trans ldmatrix
// BMD=1: B stored [j][k] (k contig)     -> smem [j][k] LDK=40, normal ldmatrix
// BMD=0: B stored [k][j] (j contig)     -> smem [k][j] LDJ=136, trans ldmatrix
// EPI=0: fp32 store *alpha | EPI=1: fp32 accumulate | EPI=2: split-store hi/lo
// Block tile 128x128, BK=32, 256 threads (8 warps of 32x64).
// ---------------------------------------------------------------------------
template<int AM, int BMD, int EPI>
__global__ __launch_bounds__(256)
void bgemm(const bf16* __restrict__ Ah, const bf16* __restrict__ Al,
           const bf16* __restrict__ Bh, const bf16* __restrict__ Bl,
           void* __restrict__ Cg, void* __restrict__ Cg2,
           int Kdim, int lda, int ldb, int ldc,
           size_t sA, size_t sB, size_t sC, float alpha)
{
    extern __shared__ bf16 sm[];
    constexpr int COMP = 5120;      // halves per component (>= max(128*40, 32*136))

    const int tid = threadIdx.x;
    const int lane = tid & 31, wid = tid >> 5;
    const int m_off = (wid & 3) * 32;
    const int n_off = (wid >> 2) * 64;
    const int i0 = blockIdx.y * 128, j0 = blockIdx.x * 128;

    const bf16* A0 = Ah + blockIdx.z * sA;
    const bf16* A1 = Al + blockIdx.z * sA;
    const bf16* B0 = Bh + blockIdx.z * sB;
    const bf16* B1 = Bl + blockIdx.z * sB;

    float acc[2][8][4];
#pragma unroll
    for (int t = 0; t < 2; t++)
#pragma unroll
        for (int n = 0; n < 8; n++)
#pragma unroll
            for (int r = 0; r < 4; r++) acc[t][n][r] = 0.f;

    auto load_stage = [&](int st, int kt) {
        bf16* sa0 = sm + st * 4 * COMP;
        bf16* sa1 = sa0 + COMP;
        bf16* sb0 = sa1 + COMP;
        bf16* sb1 = sb0 + COMP;
        const int k0 = kt * 32;
        if (AM == 0) {
#pragma unroll
            for (int p = 0; p < 2; p++) {
                int r = (tid >> 2) + p * 64, c = (tid & 3) * 8;
                size_t go = (size_t)(i0 + r) * lda + k0 + c;
                cpa16(&sa0[r * 40 + c], A0 + go);
                cpa16(&sa1[r * 40 + c], A1 + go);
            }
        } else {
#pragma unroll
            for (int p = 0; p < 2; p++) {
                int kk = (tid >> 4) + p * 16, c = (tid & 15) * 8;
                size_t go = (size_t)(k0 + kk) * lda + i0 + c;
                cpa16(&sa0[kk * 136 + c], A0 + go);
                cpa16(&sa1[kk * 136 + c], A1 + go);
            }
        }
        if (BMD == 1) {
#pragma unroll
            for (int p = 0; p < 2; p++) {
                int r = (tid >> 2) + p * 64, c = (tid & 3) * 8;
                size_t go = (size_t)(j0 + r) * ldb + k0 + c;
                cpa16(&sb0[r * 40 + c], B0 + go);
                cpa16(&sb1[r * 40 + c], B1 + go);
            }
        } else {
#pragma unroll
            for (int p = 0; p < 2; p++) {
                int kk = (tid >> 4) + p * 16, c = (tid & 15) * 8;
                size_t go = (size_t)(k0 + kk) * ldb + j0 + c;
                cpa16(&sb0[kk * 136 + c], B0 + go);
                cpa16(&sb1[kk * 136 + c], B1 + go);
            }
        }
    };

    auto compute_stage = [&](int st) {
        bf16* sa0 = sm + st * 4 * COMP;
        bf16* sa1 = sa0 + COMP;
        bf16* sb0 = sa1 + COMP;
        bf16* sb1 = sb0 + COMP;
#pragma unroll
        for (int ks = 0; ks < 32; ks += 16) {
            uint32_t ahi[2][4], alo[2][4];
#pragma unroll
            for (int t = 0; t < 2; t++) {
                int off;
                if (AM == 0)
                    off = (m_off + t * 16 + (lane & 15)) * 40 + ks + (lane >> 4) * 8;
                else
                    off = (ks + (lane & 7) + ((lane >> 4) & 1) * 8) * 136
                        + m_off + t * 16 + ((lane >> 3) & 1) * 8;
                if (AM == 0) {
                    ldm_x4(ahi[t][0], ahi[t][1], ahi[t][2], ahi[t][3], sptr(sa0 + off));
                    ldm_x4(alo[t][0], alo[t][1], alo[t][2], alo[t][3], sptr(sa1 + off));
                } else {
                    ldm_x4_t(ahi[t][0], ahi[t][1], ahi[t][2], ahi[t][3], sptr(sa0 + off));
                    ldm_x4_t(alo[t][0], alo[t][1], alo[t][2], alo[t][3], sptr(sa1 + off));
                }
            }
            uint32_t bhi[8][2], blo[8][2];
#pragma unroll
            for (int p = 0; p < 4; p++) {
                int off;
                if (BMD == 1)
                    off = (n_off + p * 16 + (lane & 15)) * 40 + ks + (lane >> 4) * 8;
                else
                    off = (ks + (lane & 7) + ((lane >> 4) & 1) * 8) * 136
                        + n_off + p * 16 + ((lane >> 3) & 1) * 8;
                uint32_t r0, r1, r2, r3;
                if (BMD == 1) ldm_x4(r0, r1, r2, r3, sptr(sb0 + off));
                else          ldm_x4_t(r0, r1, r2, r3, sptr(sb0 + off));
                bhi[2 * p][0] = r0; bhi[2 * p][1] = r2;
                bhi[2 * p + 1][0] = r1; bhi[2 * p + 1][1] = r3;
                if (BMD == 1) ldm_x4(r0, r1, r2, r3, sptr(sb1 + off));
                else          ldm_x4_t(r0, r1, r2, r3, sptr(sb1 + off));
                blo[2 * p][0] = r0; blo[2 * p][1] = r2;
                blo[2 * p + 1][0] = r1; blo[2 * p + 1][1] = r3;
            }
#pragma unroll
            for (int t = 0; t < 2; t++) {
#pragma unroll
                for (int n = 0; n < 8; n++) {
                    float* c = acc[t][n];
                    mma_bf16(c[0], c[1], c[2], c[3],
                             ahi[t][0], ahi[t][1], ahi[t][2], ahi[t][3],
                             bhi[n][0], bhi[n][1]);
                    mma_bf16(c[0], c[1], c[2], c[3],
                             ahi[t][0], ahi[t][1], ahi[t][2], ahi[t][3],
                             blo[n][0], blo[n][1]);
                    mma_bf16(c[0], c[1], c[2], c[3],
                             alo[t][0], alo[t][1], alo[t][2], alo[t][3],
                             bhi[n][0], bhi[n][1]);
                }
            }
        }
    };

    const int nt = Kdim / 32;
    load_stage(0, 0);
    cpcommit();
    for (int t = 0; t < nt; t++) {
        if (t + 1 < nt) {
            load_stage((t + 1) & 1, t + 1);
            cpcommit();
            cpwait<1>();
        } else {
            cpwait<0>();
        }
        __syncthreads();
        compute_stage(t & 1);
        __syncthreads();
    }

    // -------- epilogue --------
#pragma unroll
    for (int t = 0; t < 2; t++) {
#pragma unroll
        for (int n = 0; n < 8; n++) {
            int mg = i0 + m_off + t * 16 + (lane >> 2);
            int ng = j0 + n_off + n * 8 + (lane & 3) * 2;
            if (EPI == 2) {
                bf16* Ch = (bf16*)Cg + blockIdx.z * sC;
                bf16* Cl = (bf16*)Cg2 + blockIdx.z * sC;
#pragma unroll
                for (int r = 0; r < 2; r++) {
                    float a0 = acc[t][n][2 * r], a1 = acc[t][n][2 * r + 1];
                    bf16 h0 = __float2bfloat16(a0);
                    bf16 h1 = __float2bfloat16(a1);
                    bf16 l0 = __float2bfloat16(a0 - __bfloat162float(h0));
                    bf16 l1 = __float2bfloat16(a1 - __bfloat162float(h1));
                    size_t o = (size_t)(mg + r * 8) * ldc + ng;
                    *(bf162*)(Ch + o) = bf162(h0, h1);
                    *(bf162*)(Cl + o) = bf162(l0, l1);
                }
            } else {
                float* C = (float*)Cg + blockIdx.z * sC;
#pragma unroll
                for (int r = 0; r < 2; r++) {
                    float2 o = make_float2(acc[t][n][2 * r] * alpha,
                                           acc[t][n][2 * r + 1] * alpha);
                    float* p = &C[(size_t)(mg + r * 8) * ldc + ng];
                    if (EPI == 1) {
                        float2 q = *(const float2*)p;
                        o.x += q.x; o.y += q.y;
                    }
                    *(float2*)p = o;
                }
            }
        }
    }
}

// ---------------- softmax: fp32 energy rows -> split bf16 attention --------
__global__ __launch_bounds__(256)
void softmax_rows(const float* __restrict__ e, bf16* __restrict__ ah,
                  bf16* __restrict__ al)
{
    __shared__ float red[8];
    const size_t row = blockIdx.x;
    const float* p = e + row * (size_t)MDIM;
    const int tid = threadIdx.x;

    float4 v4 = ((const float4*)p)[tid];

    float m = fmaxf(fmaxf(v4.x, v4.y), fmaxf(v4.z, v4.w));
#pragma unroll
    for (int o = 16; o > 0; o >>= 1)
        m = fmaxf(m, __shfl_xor_sync(0xffffffffu, m, o));
    if ((tid & 31) == 0) red[tid >> 5] = m;
    __syncthreads();
    if (tid < 32) {
        float t = (tid < 8) ? red[tid] : -3.4e38f;
#pragma unroll
        for (int o = 4; o > 0; o >>= 1)
            t = fmaxf(t, __shfl_xor_sync(0xffffffffu, t, o));
        if (tid == 0) red[0] = t;
    }
    __syncthreads();
    m = red[0];
    __syncthreads();

    v4.x = __expf(v4.x - m);
    v4.y = __expf(v4.y - m);
    v4.z = __expf(v4.z - m);
    v4.w = __expf(v4.w - m);
    float s = v4.x + v4.y + v4.z + v4.w;
#pragma unroll
    for (int o = 16; o > 0; o >>= 1)
        s += __shfl_xor_sync(0xffffffffu, s, o);
    if ((tid & 31) == 0) red[tid >> 5] = s;
    __syncthreads();
    if (tid < 32) {
        float t = (tid < 8) ? red[tid] : 0.f;
#pragma unroll
        for (int o = 4; o > 0; o >>= 1)
            t += __shfl_xor_sync(0xffffffffu, t, o);
        if (tid == 0) red[0] = t;
    }
    __syncthreads();
    const float inv = 1.0f / red[0];

    v4.x *= inv; v4.y *= inv; v4.z *= inv; v4.w *= inv;

    bf16 h0 = __float2bfloat16(v4.x), h1 = __float2bfloat16(v4.y);
    bf16 h2 = __float2bfloat16(v4.z), h3 = __float2bfloat16(v4.w);
    bf16 l0 = __float2bfloat16(v4.x - __bfloat162float(h0));
    bf16 l1 = __float2bfloat16(v4.y - __bfloat162float(h1));
    bf16 l2 = __float2bfloat16(v4.z - __bfloat162float(h2));
    bf16 l3 = __float2bfloat16(v4.w - __bfloat162float(h3));
    bf162* oh = (bf162*)(ah + row * (size_t)MDIM);
    bf162* ol = (bf162*)(al + row * (size_t)MDIM);
    oh[2 * tid]     = bf162(h0, h1);
    oh[2 * tid + 1] = bf162(h2, h3);
    ol[2 * tid]     = bf162(l0, l1);
    ol[2 * tid + 1] = bf162(l2, l3);
}

// ---------------------------------------------------------------------------
extern "C" void kernel_launch(void* const* d_in, const int* in_sizes, int n_in,
                              void* d_out, int out_size)
{
    const float* pcd_up   = (const float*)d_in[0]; // [B, C, N]
    const float* pcd_down = (const float*)d_in[1]; // [B, C, M]
    const float* W[4] = { (const float*)d_in[2], (const float*)d_in[3],
                          (const float*)d_in[4], (const float*)d_in[5] };
    float* out = (float*)d_out;                    // [B, C, N]

    bf16 *wh, *wl, *xuh, *xul, *xdh, *xdl, *qh, *ql, *kh, *kl, *vh, *vl, *ah, *al;
    float* e;
    cudaGetSymbolAddress((void**)&wh, g_wh);
    cudaGetSymbolAddress((void**)&wl, g_wl);
    cudaGetSymbolAddress((void**)&xuh, g_xuh);
    cudaGetSymbolAddress((void**)&xul, g_xul);
    cudaGetSymbolAddress((void**)&xdh, g_xdh);
    cudaGetSymbolAddress((void**)&xdl, g_xdl);
    cudaGetSymbolAddress((void**)&qh, g_qh);
    cudaGetSymbolAddress((void**)&ql, g_ql);
    cudaGetSymbolAddress((void**)&kh, g_kh);
    cudaGetSymbolAddress((void**)&kl, g_kl);
    cudaGetSymbolAddress((void**)&vh, g_vh);
    cudaGetSymbolAddress((void**)&vl, g_vl);
    cudaGetSymbolAddress((void**)&ah, g_ah);
    cudaGetSymbolAddress((void**)&al, g_al);
    cudaGetSymbolAddress((void**)&e, g_e);

    const size_t sUp = (size_t)CDIM * NDIM;
    const size_t sDn = (size_t)CDIM * MDIM;
    const size_t sE  = (size_t)NDIM * MDIM;
    const int smemB = 2 * 4 * 5120 * 2;  // 81920 bytes

    static bool attrDone = false;
    if (!attrDone) {
        cudaFuncSetAttribute(bgemm<0, 0, 2>, cudaFuncAttributeMaxDynamicSharedMemorySize, smemB);
        cudaFuncSetAttribute(bgemm<0, 0, 0>, cudaFuncAttributeMaxDynamicSharedMemorySize, smemB);
        cudaFuncSetAttribute(bgemm<1, 0, 0>, cudaFuncAttributeMaxDynamicSharedMemorySize, smemB);
        cudaFuncSetAttribute(bgemm<0, 1, 1>, cudaFuncAttributeMaxDynamicSharedMemorySize, smemB);
        attrDone = true;
    }

    // ---- pre-split inputs to bf16 hi/lo ----
    for (int w = 0; w < 4; w++)
        splitf<<<(CDIM * CDIM / 4 + 255) / 256, 256>>>(
            W[w], wh + (size_t)w * CDIM * CDIM, wl + (size_t)w * CDIM * CDIM,
            CDIM * CDIM / 4);
    {
        size_t n4 = (size_t)BATCH * sUp / 4;
        splitf<<<(unsigned)((n4 + 255) / 256), 256>>>(pcd_up, xuh, xul, n4);
        n4 = (size_t)BATCH * sDn / 4;
        splitf<<<(unsigned)((n4 + 255) / 256), 256>>>(pcd_down, xdh, xdl, n4);
    }

    const float invSqrtC = 0.044194173824159216f; // 1/sqrt(512)

    // q = Wq @ pcd_up (split out); skip = Wskip @ pcd_up -> out (fp32)
    {
        dim3 grid(NDIM / 128, CDIM / 128, BATCH);
        bgemm<0, 0, 2><<<grid, 256, smemB>>>(
            wh, wl, xuh, xul, qh, ql, CDIM, CDIM, NDIM, NDIM, 0, sUp, sUp, 1.0f);
        bgemm<0, 0, 0><<<grid, 256, smemB>>>(
            wh + 3 * (size_t)CDIM * CDIM, wl + 3 * (size_t)CDIM * CDIM,
            xuh, xul, out, nullptr, CDIM, CDIM, NDIM, NDIM, 0, sUp, sUp, 1.0f);
    }
    // k, v (split out)
    {
        dim3 grid(MDIM / 128, CDIM / 128, BATCH);
        bgemm<0, 0, 2><<<grid, 256, smemB>>>(
            wh + 1 * (size_t)CDIM * CDIM, wl + 1 * (size_t)CDIM * CDIM,
            xdh, xdl, kh, kl, CDIM, CDIM, MDIM, MDIM, 0, sDn, sDn, 1.0f);
        bgemm<0, 0, 2><<<grid, 256, smemB>>>(
            wh + 2 * (size_t)CDIM * CDIM, wl + 2 * (size_t)CDIM * CDIM,
            xdh, xdl, vh, vl, CDIM, CDIM, MDIM, MDIM, 0, sDn, sDn, 1.0f);
    }
    // energy[n,m] = (1/sqrt(C)) * sum_c q[c,n] k[c,m]  (A trans-layout)
    {
        dim3 grid(MDIM / 128, NDIM / 128, BATCH);
        bgemm<1, 0, 0><<<grid, 256, smemB>>>(
            qh, ql, kh, kl, e, nullptr, CDIM, NDIM, MDIM, MDIM, sUp, sDn, sE, invSqrtC);
    }
    // softmax -> split attention
    softmax_rows<<<BATCH * NDIM, 256>>>(e, ah, al);

    // out[c,n] += sum_m v[c,m] * attn[n,m]  (B normal [j][k] layout)
    {
        dim3 grid(NDIM / 128, CDIM / 128, BATCH);
        bgemm<0, 1, 1><<<grid, 256, smemB>>>(
            vh, vl, ah, al, out, nullptr, MDIM, MDIM, MDIM, NDIM, sDn, sE, sUp, 1.0f);
    }
}